// round 6
// baseline (speedup 1.0000x reference)
#include <cuda_runtime.h>

#define NPTS 6000
#define NTRI 16000
#define NMOV 4000
#define NBND 1500
#define BB   16
#define KC   320                       // t per smem chunk; 2 bufs * 8 planes * 320 * 8B = 40KB
#define NCH  (NTRI / KC)               // 50 chunks
#define NGRP (NTRI / 64)               // 250 groups of 64 t
#define EPSV 1e-8f

// ---------------- scratch (static __device__, no allocation) ----------------
__device__ float g_pz[BB * NPTS * 3];                 // working point cloud [b][p][xyz]
__device__ unsigned long long g_Dp[8 * NTRI];         // D as 8 batch-pair planes [p][t] (float2)
__device__ float g_C [NMOV * BB];                     // GEMM output [m][b]
__device__ int   g_w1[NPTS];
__device__ int   g_w2[NPTS];
__device__ float g_vols[BB];
__device__ float g_volc;
__device__ float g_ssq[BB];

// ---------------- f32x2 packed-math helpers ----------------
__device__ __forceinline__ unsigned long long splat2(float f) {
    unsigned long long r;
    asm("mov.b64 %0, {%1, %1};" : "=l"(r) : "r"(__float_as_uint(f)));
    return r;
}
__device__ __forceinline__ unsigned long long fma2(unsigned long long a,
                                                   unsigned long long b,
                                                   unsigned long long c) {
    unsigned long long d;
    asm("fma.rn.f32x2 %0, %1, %2, %3;" : "=l"(d) : "l"(a), "l"(b), "l"(c));
    return d;
}
__device__ __forceinline__ float lo32(unsigned long long u) {
    return __int_as_float((int)(unsigned)(u & 0xffffffffull));
}
__device__ __forceinline__ float hi32(unsigned long long u) {
    return __int_as_float((int)(unsigned)(u >> 32));
}

// ---------------- setup: init + winner maps (single block, internally ordered) ----
__global__ void k_setup(const int* __restrict__ idx1, const int* __restrict__ idx2) {
    int tid = threadIdx.x;
    for (int i = tid; i < NPTS; i += 1024) { g_w1[i] = -1; g_w2[i] = -1; }
    if (tid < BB) g_vols[tid] = 0.f;
    if (tid == 0) g_volc = 0.f;
    __syncthreads();
    for (int i = tid; i < NMOV; i += 1024) atomicMax(&g_w1[idx1[i]], i);
    for (int i = tid; i < NBND; i += 1024) atomicMax(&g_w2[idx2[i]], i);
}

// ---------------- build pz + copy x -> out ----------------
__global__ void k_pzcopy(const float* __restrict__ x, const float* __restrict__ y,
                         const float* __restrict__ p0, float* __restrict__ out) {
    int i = blockIdx.x * blockDim.x + threadIdx.x;
    if (i < BB * NMOV * 3) out[i] = x[i];
    if (i >= BB * NPTS) return;
    int b = i / NPTS, p = i - b * NPTS;
    float vx = p0[p * 3 + 0], vy = p0[p * 3 + 1], vz = p0[p * 3 + 2];
    int w2 = g_w2[p];
    if (w2 >= 0) {
        vx = y[b * 2 * NBND + 2 * w2 + 0];
        vz = y[b * 2 * NBND + 2 * w2 + 1];
    }
    int w1 = g_w1[p];
    if (w1 >= 0) {
        const float* xr = x + (size_t)(b * NMOV + w1) * 3;
        vx = xr[0]; vy = xr[1]; vz = xr[2];
    }
    float* o = g_pz + (size_t)(b * NPTS + p) * 3;
    o[0] = vx; o[1] = vy; o[2] = vz;
}

// ---------------- fused pre-pass: D(axis=2) + vols + volc + ssq zero ----------------
__global__ void k_pre(const float* __restrict__ p0, const int* __restrict__ tri) {
    int i = blockIdx.x * blockDim.x + threadIdx.x;
    if (blockIdx.x == 0 && threadIdx.x < BB) g_ssq[threadIdx.x] = 0.f;
    __shared__ float sacc[BB];
    __shared__ float svolc;
    if (threadIdx.x < BB) sacc[threadIdx.x] = 0.f;
    if (threadIdx.x == 0) svolc = 0.f;
    __syncthreads();

    float vterm = 0.f;
    if (i < NTRI * BB) {
        int b = i / NTRI, t = i - b * NTRI;
        int i0 = tri[t * 3 + 0], i1 = tri[t * 3 + 1], i2 = tri[t * 3 + 2];
        const float* P = g_pz + (size_t)b * NPTS * 3;
        float x0 = P[i0 * 3], y0 = P[i0 * 3 + 1], z0 = P[i0 * 3 + 2];
        float x1 = P[i1 * 3], y1 = P[i1 * 3 + 1], z1 = P[i1 * 3 + 2];
        float x2 = P[i2 * 3], y2 = P[i2 * 3 + 1], z2 = P[i2 * 3 + 2];
        // D for axis 2 (needs x,y)
        float d2 = ((x0 - x2) * (y1 - y2) - (y0 - y2) * (x1 - x2)) * (1.f / 6.f);
        ((float*)g_Dp)[(((size_t)(b >> 1) * NTRI + t) << 1) + (b & 1)] = d2;
        // vols contribution (x-volume: det over y,z)
        float dv = ((y1 - y0) * (z2 - z0) - (z1 - z0) * (y2 - y0)) * (1.f / 6.f);
        atomicAdd(&sacc[b], (x0 + x1 + x2) * dv);
        // volc (reference mesh) from b==0 threads only
        if (b == 0) {
            float qx0 = p0[i0 * 3], qy0 = p0[i0 * 3 + 1], qz0 = p0[i0 * 3 + 2];
            float qx1 = p0[i1 * 3], qy1 = p0[i1 * 3 + 1], qz1 = p0[i1 * 3 + 2];
            float qx2 = p0[i2 * 3], qy2 = p0[i2 * 3 + 1], qz2 = p0[i2 * 3 + 2];
            float dd = ((qy1 - qy0) * (qz2 - qz0) - (qz1 - qz0) * (qy2 - qy0)) * (1.f / 6.f);
            vterm = (qx0 + qx1 + qx2) * dd;
        }
    }
    if ((int)(blockIdx.x * blockDim.x) < NTRI) {      // only blocks containing b==0 threads
        #pragma unroll
        for (int off = 16; off; off >>= 1) vterm += __shfl_xor_sync(0xffffffffu, vterm, off);
        if ((threadIdx.x & 31) == 0 && vterm != 0.f) atomicAdd(&svolc, vterm);
    }
    __syncthreads();
    if (threadIdx.x < BB && sacc[threadIdx.x] != 0.f)
        atomicAdd(&g_vols[threadIdx.x], sacc[threadIdx.x]);
    if (threadIdx.x == 0 && svolc != 0.f) atomicAdd(&g_volc, svolc);
}

// ---------------- per-axis D (axes 1 and 0) ----------------
__global__ void k_D(const int* __restrict__ tri, int axis) {
    int i = blockIdx.x * blockDim.x + threadIdx.x;
    if (blockIdx.x == 0 && threadIdx.x < BB) g_ssq[threadIdx.x] = 0.f;
    if (i >= NTRI * BB) return;
    int b = i / NTRI, t = i - b * NTRI;
    int i0 = tri[t * 3 + 0], i1 = tri[t * 3 + 1], i2 = tri[t * 3 + 2];
    const float* P = g_pz + (size_t)b * NPTS * 3;
    float d;
    if (axis == 1) {      // needs x,z
        float x0 = P[i0 * 3], z0 = P[i0 * 3 + 2];
        float x1 = P[i1 * 3], z1 = P[i1 * 3 + 2];
        float x2 = P[i2 * 3], z2 = P[i2 * 3 + 2];
        d = ((x0 - x1) * (z2 - z1) - (z0 - z1) * (x2 - x1)) * (1.f / 6.f);
    } else {              // axis 0: needs y,z
        float y0 = P[i0 * 3 + 1], z0 = P[i0 * 3 + 2];
        float y1 = P[i1 * 3 + 1], z1 = P[i1 * 3 + 2];
        float y2 = P[i2 * 3 + 1], z2 = P[i2 * 3 + 2];
        d = ((y1 - y0) * (z2 - z0) - (z1 - z0) * (y2 - y0)) * (1.f / 6.f);
    }
    ((float*)g_Dp)[(((size_t)(b >> 1) * NTRI + t) << 1) + (b & 1)] = d;
}

// ---------------- cp.async helpers ----------------
__device__ __forceinline__ void cp16(unsigned smem_addr, const void* gptr) {
    asm volatile("cp.async.cg.shared.global [%0], [%1], 16;"
                 :: "r"(smem_addr), "l"(gptr));
}
__device__ __forceinline__ void cp_commit() { asm volatile("cp.async.commit_group;"); }
__device__ __forceinline__ void cp_wait1()  { asm volatile("cp.async.wait_group 1;"); }
__device__ __forceinline__ void cp_wait0()  { asm volatile("cp.async.wait_group 0;"); }

// ---------------- skinny GEMM: C[m][b] = sum_t Vf[m][t] * D[t][b] ----------------
// 250 blocks x 128 thr; warp owns 4 rows; lane owns t-pair (2l,2l+1) per 64-t group.
// D: LDS.128 on pair-planes (16B lane stride, conflict-free). Vf: LDG.64 float2,
// prefetch depth 2 groups. ssq accumulated via block-reduced atomics.
__global__ __launch_bounds__(128) void k_gemm(const float* __restrict__ Vf) {
    __shared__ unsigned long long Ds[2 * 8 * KC];
    __shared__ float ssq_s[BB];
    const int tid = threadIdx.x;
    const int warp = tid >> 5, lane = tid & 31;
    const int row0 = blockIdx.x * 16 + warp * 4;
    if (tid < BB) ssq_s[tid] = 0.f;

    const unsigned smem_base = (unsigned)__cvta_generic_to_shared(Ds);

    auto stage = [&](int chunk, int buf) {
        const char* gbase = (const char*)g_Dp;
        unsigned sbase = smem_base + (unsigned)buf * (8 * KC * 8);
        #pragma unroll
        for (int i = 0; i < (8 * KC / 2) / 128; i++) {
            int idx = tid + i * 128;
            int p = idx / (KC / 2);
            int off = idx - p * (KC / 2);
            cp16(sbase + (unsigned)(p * KC + off * 2) * 8,
                 gbase + ((size_t)p * NTRI + (size_t)chunk * KC) * 8 + (size_t)off * 16);
        }
        cp_commit();
    };

    unsigned long long acc[4][8];
    #pragma unroll
    for (int r = 0; r < 4; r++)
        #pragma unroll
        for (int p = 0; p < 8; p++) acc[r][p] = 0ull;

    stage(0, 0);

    // Vf as float2 stream; pair index for group G is G*32 + lane
    const float2* vrow[4];
    #pragma unroll
    for (int r = 0; r < 4; r++)
        vrow[r] = (const float2*)(Vf + (size_t)(row0 + r) * NTRI) + lane;

    float2 va[4], vb[4], vc[4];
    #pragma unroll
    for (int r = 0; r < 4; r++) {
        va[r] = __ldcs(&vrow[r][0 * 32]);
        vb[r] = __ldcs(&vrow[r][1 * 32]);
    }

    for (int c = 0; c < NCH; c++) {
        int buf = c & 1;
        if (c + 1 < NCH) { stage(c + 1, buf ^ 1); cp_wait1(); }
        else             { cp_wait0(); }
        __syncthreads();

        const unsigned long long* dsb = Ds + (size_t)buf * 8 * KC;
        #pragma unroll
        for (int g = 0; g < KC / 64; g++) {          // 5 groups of 64 t
            int G = c * (KC / 64) + g;
            if (G + 2 < NGRP) {
                #pragma unroll
                for (int r = 0; r < 4; r++) vc[r] = __ldcs(&vrow[r][(G + 2) * 32]);
            }
            ulonglong2 dv[8];
            const ulonglong2* dpb =
                (const ulonglong2*)(dsb + g * 64 + 2 * lane);
            #pragma unroll
            for (int p = 0; p < 8; p++)
                dv[p] = dpb[(size_t)p * (KC / 2)];
            #pragma unroll
            for (int r = 0; r < 4; r++) {
                unsigned long long s0 = splat2(va[r].x);
                unsigned long long s1 = splat2(va[r].y);
                #pragma unroll
                for (int p = 0; p < 8; p++) {
                    acc[r][p] = fma2(s0, dv[p].x, acc[r][p]);
                    acc[r][p] = fma2(s1, dv[p].y, acc[r][p]);
                }
            }
            #pragma unroll
            for (int r = 0; r < 4; r++) { va[r] = vb[r]; vb[r] = vc[r]; }
        }
        __syncthreads();
    }

    // reduce across the 32 lanes; lane b (<16) keeps its batch value
    float sel[4];
    #pragma unroll
    for (int r = 0; r < 4; r++) sel[r] = 0.f;
    #pragma unroll
    for (int r = 0; r < 4; r++)
        #pragma unroll
        for (int p = 0; p < 8; p++) {
            float l = lo32(acc[r][p]), h = hi32(acc[r][p]);
            #pragma unroll
            for (int off = 16; off; off >>= 1) {
                l += __shfl_xor_sync(0xffffffffu, l, off);
                h += __shfl_xor_sync(0xffffffffu, h, off);
            }
            if ((lane >> 1) == p) sel[r] = (lane & 1) ? h : l;
        }

    if (lane < BB) {
        float sq = 0.f;
        #pragma unroll
        for (int r = 0; r < 4; r++) {
            g_C[(size_t)(row0 + r) * BB + lane] = sel[r];
            sq += sel[r] * sel[r];
        }
        atomicAdd(&ssq_s[lane], sq);
    }
    __syncthreads();
    if (tid < BB) atomicAdd(&g_ssq[tid], ssq_s[tid]);
}

// ---------------- per-axis: solve + update pts + maintain pz (a computed inline) ----
__global__ void k_update(const int* __restrict__ idx1, float* __restrict__ out, int axis) {
    int i = blockIdx.x * blockDim.x + threadIdx.x;
    if (i >= NMOV * BB) return;
    int m = i % NMOV, b = i / NMOV;
    float c = g_C[(size_t)m * BB + b];
    float a = (g_volc - g_vols[b]) * (1.f / 3.f);
    float s = a / (g_ssq[b] + EPSV);
    size_t o = (size_t)(b * NMOV + m) * 3 + axis;
    float nv = out[o] + c * s;
    out[o] = nv;
    int p = idx1[m];
    if (g_w1[p] == m) g_pz[(size_t)(b * NPTS + p) * 3 + axis] = nv;
}

// ---------------- launch ----------------
extern "C" void kernel_launch(void* const* d_in, const int* in_sizes, int n_in,
                              void* d_out, int out_size) {
    const float* x   = (const float*)d_in[0];
    const float* y   = (const float*)d_in[1];
    const float* p0  = (const float*)d_in[2];
    const float* Vf  = (const float*)d_in[3];
    const int* idx1  = (const int*)d_in[4];
    const int* idx2  = (const int*)d_in[5];
    const int* tri   = (const int*)d_in[6];
    float* out       = (float*)d_out;

    k_setup  <<<1, 1024>>>(idx1, idx2);                         // 1
    k_pzcopy <<<(BB * NMOV * 3 + 255) / 256, 256>>>(x, y, p0, out); // 2
    k_pre    <<<(NTRI * BB + 255) / 256, 256>>>(p0, tri);       // 3 (D axis2 + vols + volc)
    k_gemm   <<<NMOV / 16, 128>>>(Vf);                          // 4 <- ncu sample slot
    k_update <<<(NMOV * BB + 255) / 256, 256>>>(idx1, out, 2);  // 5

    k_D      <<<(NTRI * BB + 255) / 256, 256>>>(tri, 1);        // 6
    k_gemm   <<<NMOV / 16, 128>>>(Vf);                          // 7
    k_update <<<(NMOV * BB + 255) / 256, 256>>>(idx1, out, 1);  // 8

    k_D      <<<(NTRI * BB + 255) / 256, 256>>>(tri, 0);        // 9
    k_gemm   <<<NMOV / 16, 128>>>(Vf);                          // 10
    k_update <<<(NMOV * BB + 255) / 256, 256>>>(idx1, out, 0);  // 11
}

// round 7
// speedup vs baseline: 2.0225x; 2.0225x over previous
#include <cuda_runtime.h>

#define NPTS 6000
#define NTRI 16000
#define NTRIP 16384                    // padded triangle count (pad D = 0)
#define NMOV 4000
#define NBND 1500
#define BB   16
#define KSPLIT 4
#define KSLICE (NTRIP / KSPLIT)        // 4096 t per slice
#define KC   256                       // t per smem chunk; 2 bufs * 8 planes * 256 * 8B = 32KB
#define NCHS (KSLICE / KC)             // 16 chunks per slice
#define GPC  (KC / 64)                 // 4 groups of 64 t per chunk
#define EPSV 1e-8f

// ---------------- scratch (static __device__, no allocation) ----------------
__device__ float g_pz[BB * NPTS * 3];                 // working point cloud [b][p][xyz]
__device__ unsigned long long g_Dp[8 * NTRIP];        // D as 8 batch-pair planes [p][t]
__device__ float g_Cp[KSPLIT][NMOV * BB];             // per-slice partial C [m][b]
__device__ float g_C [NMOV * BB];                     // merged C [m][b]
__device__ int   g_w1[NPTS];
__device__ int   g_w2[NPTS];
__device__ float g_vols[BB];
__device__ float g_volc;
__device__ float g_ssq[BB];

// ---------------- f32x2 packed-math helpers ----------------
__device__ __forceinline__ unsigned long long splat2(float f) {
    unsigned long long r;
    asm("mov.b64 %0, {%1, %1};" : "=l"(r) : "r"(__float_as_uint(f)));
    return r;
}
__device__ __forceinline__ unsigned long long fma2(unsigned long long a,
                                                   unsigned long long b,
                                                   unsigned long long c) {
    unsigned long long d;
    asm("fma.rn.f32x2 %0, %1, %2, %3;" : "=l"(d) : "l"(a), "l"(b), "l"(c));
    return d;
}
__device__ __forceinline__ float lo32(unsigned long long u) {
    return __int_as_float((int)(unsigned)(u & 0xffffffffull));
}
__device__ __forceinline__ float hi32(unsigned long long u) {
    return __int_as_float((int)(unsigned)(u >> 32));
}

// ---------------- setup: init + winner maps + D pad zero (single block) ----------
__global__ void k_setup(const int* __restrict__ idx1, const int* __restrict__ idx2) {
    int tid = threadIdx.x;
    for (int i = tid; i < NPTS; i += 1024) { g_w1[i] = -1; g_w2[i] = -1; }
    // zero the t-pad of all 8 planes once; per-axis D writes never touch it
    for (int i = tid; i < 8 * (NTRIP - NTRI); i += 1024) {
        int p = i / (NTRIP - NTRI), t = NTRI + i % (NTRIP - NTRI);
        g_Dp[(size_t)p * NTRIP + t] = 0ull;
    }
    if (tid < BB) g_vols[tid] = 0.f;
    if (tid == 0) g_volc = 0.f;
    __syncthreads();
    for (int i = tid; i < NMOV; i += 1024) atomicMax(&g_w1[idx1[i]], i);
    for (int i = tid; i < NBND; i += 1024) atomicMax(&g_w2[idx2[i]], i);
}

// ---------------- build pz + copy x -> out ----------------
__global__ void k_pzcopy(const float* __restrict__ x, const float* __restrict__ y,
                         const float* __restrict__ p0, float* __restrict__ out) {
    int i = blockIdx.x * blockDim.x + threadIdx.x;
    if (i < BB * NMOV * 3) out[i] = x[i];
    if (i >= BB * NPTS) return;
    int b = i / NPTS, p = i - b * NPTS;
    float vx = p0[p * 3 + 0], vy = p0[p * 3 + 1], vz = p0[p * 3 + 2];
    int w2 = g_w2[p];
    if (w2 >= 0) {
        vx = y[b * 2 * NBND + 2 * w2 + 0];
        vz = y[b * 2 * NBND + 2 * w2 + 1];
    }
    int w1 = g_w1[p];
    if (w1 >= 0) {
        const float* xr = x + (size_t)(b * NMOV + w1) * 3;
        vx = xr[0]; vy = xr[1]; vz = xr[2];
    }
    float* o = g_pz + (size_t)(b * NPTS + p) * 3;
    o[0] = vx; o[1] = vy; o[2] = vz;
}

// ---------------- fused pre-pass: D(axis=2) + vols + volc + ssq zero ----------------
__global__ void k_pre(const float* __restrict__ p0, const int* __restrict__ tri) {
    int i = blockIdx.x * blockDim.x + threadIdx.x;
    if (blockIdx.x == 0 && threadIdx.x < BB) g_ssq[threadIdx.x] = 0.f;
    __shared__ float sacc[BB];
    __shared__ float svolc;
    if (threadIdx.x < BB) sacc[threadIdx.x] = 0.f;
    if (threadIdx.x == 0) svolc = 0.f;
    __syncthreads();

    float vterm = 0.f;
    if (i < NTRI * BB) {
        int b = i / NTRI, t = i - b * NTRI;
        int i0 = tri[t * 3 + 0], i1 = tri[t * 3 + 1], i2 = tri[t * 3 + 2];
        const float* P = g_pz + (size_t)b * NPTS * 3;
        float x0 = P[i0 * 3], y0 = P[i0 * 3 + 1], z0 = P[i0 * 3 + 2];
        float x1 = P[i1 * 3], y1 = P[i1 * 3 + 1], z1 = P[i1 * 3 + 2];
        float x2 = P[i2 * 3], y2 = P[i2 * 3 + 1], z2 = P[i2 * 3 + 2];
        float d2 = ((x0 - x2) * (y1 - y2) - (y0 - y2) * (x1 - x2)) * (1.f / 6.f);
        ((float*)g_Dp)[(((size_t)(b >> 1) * NTRIP + t) << 1) + (b & 1)] = d2;
        float dv = ((y1 - y0) * (z2 - z0) - (z1 - z0) * (y2 - y0)) * (1.f / 6.f);
        atomicAdd(&sacc[b], (x0 + x1 + x2) * dv);
        if (b == 0) {
            float qx0 = p0[i0 * 3], qy0 = p0[i0 * 3 + 1], qz0 = p0[i0 * 3 + 2];
            float qx1 = p0[i1 * 3], qy1 = p0[i1 * 3 + 1], qz1 = p0[i1 * 3 + 2];
            float qx2 = p0[i2 * 3], qy2 = p0[i2 * 3 + 1], qz2 = p0[i2 * 3 + 2];
            float dd = ((qy1 - qy0) * (qz2 - qz0) - (qz1 - qz0) * (qy2 - qy0)) * (1.f / 6.f);
            vterm = (qx0 + qx1 + qx2) * dd;
        }
    }
    if ((int)(blockIdx.x * blockDim.x) < NTRI) {
        #pragma unroll
        for (int off = 16; off; off >>= 1) vterm += __shfl_xor_sync(0xffffffffu, vterm, off);
        if ((threadIdx.x & 31) == 0 && vterm != 0.f) atomicAdd(&svolc, vterm);
    }
    __syncthreads();
    if (threadIdx.x < BB && sacc[threadIdx.x] != 0.f)
        atomicAdd(&g_vols[threadIdx.x], sacc[threadIdx.x]);
    if (threadIdx.x == 0 && svolc != 0.f) atomicAdd(&g_volc, svolc);
}

// ---------------- per-axis D (axes 1 and 0) ----------------
__global__ void k_D(const int* __restrict__ tri, int axis) {
    int i = blockIdx.x * blockDim.x + threadIdx.x;
    if (blockIdx.x == 0 && threadIdx.x < BB) g_ssq[threadIdx.x] = 0.f;
    if (i >= NTRI * BB) return;
    int b = i / NTRI, t = i - b * NTRI;
    int i0 = tri[t * 3 + 0], i1 = tri[t * 3 + 1], i2 = tri[t * 3 + 2];
    const float* P = g_pz + (size_t)b * NPTS * 3;
    float d;
    if (axis == 1) {      // needs x,z
        float x0 = P[i0 * 3], z0 = P[i0 * 3 + 2];
        float x1 = P[i1 * 3], z1 = P[i1 * 3 + 2];
        float x2 = P[i2 * 3], z2 = P[i2 * 3 + 2];
        d = ((x0 - x1) * (z2 - z1) - (z0 - z1) * (x2 - x1)) * (1.f / 6.f);
    } else {              // axis 0: needs y,z
        float y0 = P[i0 * 3 + 1], z0 = P[i0 * 3 + 2];
        float y1 = P[i1 * 3 + 1], z1 = P[i1 * 3 + 2];
        float y2 = P[i2 * 3 + 1], z2 = P[i2 * 3 + 2];
        d = ((y1 - y0) * (z2 - z0) - (z1 - z0) * (y2 - y0)) * (1.f / 6.f);
    }
    ((float*)g_Dp)[(((size_t)(b >> 1) * NTRIP + t) << 1) + (b & 1)] = d;
}

// ---------------- cp.async helpers ----------------
__device__ __forceinline__ void cp16(unsigned smem_addr, const void* gptr) {
    asm volatile("cp.async.cg.shared.global [%0], [%1], 16;"
                 :: "r"(smem_addr), "l"(gptr));
}
__device__ __forceinline__ void cp_commit() { asm volatile("cp.async.commit_group;"); }
__device__ __forceinline__ void cp_wait1()  { asm volatile("cp.async.wait_group 1;"); }
__device__ __forceinline__ void cp_wait0()  { asm volatile("cp.async.wait_group 0;"); }

// ---------------- skinny GEMM, K-split 4 ----------------
// Cp[s][m][b] = sum_{t in slice s} Vf[m][t] * D[t][b]
// 1000 blocks (250 row-tiles x 4 slices) x 128 thr; warp owns 4 rows; lane owns
// a t-pair per 64-t group. D: LDS.128 on pair-planes (conflict-free). Vf: LDG.64
// float2 with depth-4 STATIC prefetch rotation (buffer index == group-in-chunk).
__global__ __launch_bounds__(128, 3) void k_gemm(const float* __restrict__ Vf) {
    __shared__ unsigned long long Ds[2 * 8 * KC];     // 32KB
    const int tid = threadIdx.x;
    const int warp = tid >> 5, lane = tid & 31;
    const int rt = blockIdx.x >> 2;
    const int s  = blockIdx.x & 3;
    const int row0 = rt * 16 + warp * 4;
    const int tb      = s * KSLICE;       // ull (t) base into planes
    const int tb_pair = s * (KSLICE / 2); // float2 base index into Vf rows

    const unsigned smem_base = (unsigned)__cvta_generic_to_shared(Ds);

    auto stage = [&](int chunk, int buf) {
        const char* gbase = (const char*)g_Dp;
        unsigned sbase = smem_base + (unsigned)buf * (8 * KC * 8);
        #pragma unroll
        for (int i = 0; i < (8 * KC / 2) / 128; i++) {        // 8 per thread
            int idx = tid + i * 128;
            int p = idx >> 7;                                 // idx / (KC/2)
            int off = idx & 127;
            cp16(sbase + (unsigned)(p * KC + off * 2) * 8,
                 gbase + ((size_t)p * NTRIP + (size_t)tb + (size_t)chunk * KC) * 8
                       + (size_t)off * 16);
        }
        cp_commit();
    };

    unsigned long long acc[4][8];
    #pragma unroll
    for (int r = 0; r < 4; r++)
        #pragma unroll
        for (int p = 0; p < 8; p++) acc[r][p] = 0ull;

    stage(0, 0);

    const float2* vrow[4];
    #pragma unroll
    for (int r = 0; r < 4; r++)
        vrow[r] = (const float2*)(Vf + (size_t)(row0 + r) * NTRI);

    // depth-4 static prefetch: pre[g] holds Vf pairs for group g of current chunk
    float2 pre[GPC][4];
    #pragma unroll
    for (int g = 0; g < GPC; g++) {
        int pi = tb_pair + g * 32 + lane;
        if (pi > NTRI / 2 - 1) pi = NTRI / 2 - 1;             // clamp into valid Vf
        #pragma unroll
        for (int r = 0; r < 4; r++) pre[g][r] = __ldcs(&vrow[r][pi]);
    }

    for (int c = 0; c < NCHS; c++) {
        int buf = c & 1;
        if (c + 1 < NCHS) { stage(c + 1, buf ^ 1); cp_wait1(); }
        else              { cp_wait0(); }
        __syncthreads();

        const unsigned long long* dsb = Ds + (size_t)buf * 8 * KC;
        #pragma unroll
        for (int g = 0; g < GPC; g++) {
            // splat current group's Vf values BEFORE refilling the buffer
            unsigned long long s0[4], s1[4];
            #pragma unroll
            for (int r = 0; r < 4; r++) {
                s0[r] = splat2(pre[g][r].x);
                s1[r] = splat2(pre[g][r].y);
            }
            // refill slot g for the same group of chunk c+1 (clamped; unused on last)
            {
                int pi = tb_pair + ((c + 1) * GPC + g) * 32 + lane;
                if (pi > NTRI / 2 - 1) pi = NTRI / 2 - 1;
                #pragma unroll
                for (int r = 0; r < 4; r++) pre[g][r] = __ldcs(&vrow[r][pi]);
            }
            const unsigned long long* dpb = dsb + g * 64 + 2 * lane;
            #pragma unroll
            for (int h = 0; h < 2; h++) {
                ulonglong2 dv[4];
                #pragma unroll
                for (int q = 0; q < 4; q++)
                    dv[q] = *(const ulonglong2*)(dpb + (size_t)(h * 4 + q) * KC);
                #pragma unroll
                for (int r = 0; r < 4; r++)
                    #pragma unroll
                    for (int q = 0; q < 4; q++) {
                        acc[r][h * 4 + q] = fma2(s0[r], dv[q].x, acc[r][h * 4 + q]);
                        acc[r][h * 4 + q] = fma2(s1[r], dv[q].y, acc[r][h * 4 + q]);
                    }
            }
        }
        __syncthreads();
    }

    // reduce across the 32 lanes; lane b (<16) keeps its batch value
    float sel[4];
    #pragma unroll
    for (int r = 0; r < 4; r++) sel[r] = 0.f;
    #pragma unroll
    for (int r = 0; r < 4; r++)
        #pragma unroll
        for (int p = 0; p < 8; p++) {
            float l = lo32(acc[r][p]), h = hi32(acc[r][p]);
            #pragma unroll
            for (int off = 16; off; off >>= 1) {
                l += __shfl_xor_sync(0xffffffffu, l, off);
                h += __shfl_xor_sync(0xffffffffu, h, off);
            }
            if ((lane >> 1) == p) sel[r] = (lane & 1) ? h : l;
        }

    if (lane < BB) {
        float* dst = g_Cp[s];
        #pragma unroll
        for (int r = 0; r < 4; r++)
            dst[(size_t)(row0 + r) * BB + lane] = sel[r];
    }
}

// ---------------- merge slices, compute C and per-batch sum of squares ----------
__global__ void k_ssq() {
    __shared__ float sacc[BB];
    if (threadIdx.x < BB) sacc[threadIdx.x] = 0.f;
    __syncthreads();
    int i = blockIdx.x * blockDim.x + threadIdx.x;
    if (i < NMOV * BB) {
        float c = g_Cp[0][i] + g_Cp[1][i] + g_Cp[2][i] + g_Cp[3][i];
        g_C[i] = c;
        atomicAdd(&sacc[i & 15], c * c);
    }
    __syncthreads();
    if (threadIdx.x < BB) atomicAdd(&g_ssq[threadIdx.x], sacc[threadIdx.x]);
}

// ---------------- per-axis: solve + update pts + maintain pz ----------------
__global__ void k_update(const int* __restrict__ idx1, float* __restrict__ out, int axis) {
    int i = blockIdx.x * blockDim.x + threadIdx.x;
    if (i >= NMOV * BB) return;
    int m = i % NMOV, b = i / NMOV;
    float c = g_C[(size_t)m * BB + b];
    float a = (g_volc - g_vols[b]) * (1.f / 3.f);
    float s = a / (g_ssq[b] + EPSV);
    size_t o = (size_t)(b * NMOV + m) * 3 + axis;
    float nv = out[o] + c * s;
    out[o] = nv;
    int p = idx1[m];
    if (g_w1[p] == m) g_pz[(size_t)(b * NPTS + p) * 3 + axis] = nv;
}

// ---------------- launch ----------------
extern "C" void kernel_launch(void* const* d_in, const int* in_sizes, int n_in,
                              void* d_out, int out_size) {
    const float* x   = (const float*)d_in[0];
    const float* y   = (const float*)d_in[1];
    const float* p0  = (const float*)d_in[2];
    const float* Vf  = (const float*)d_in[3];
    const int* idx1  = (const int*)d_in[4];
    const int* idx2  = (const int*)d_in[5];
    const int* tri   = (const int*)d_in[6];
    float* out       = (float*)d_out;

    k_setup  <<<1, 1024>>>(idx1, idx2);
    k_pzcopy <<<(BB * NMOV * 3 + 255) / 256, 256>>>(x, y, p0, out);
    k_pre    <<<(NTRI * BB + 255) / 256, 256>>>(p0, tri);       // D axis2 + vols + volc + ssq=0
    k_gemm   <<<(NMOV / 16) * KSPLIT, 128>>>(Vf);               // launch #4 (ncu slot)
    k_ssq    <<<(NMOV * BB + 255) / 256, 256>>>();
    k_update <<<(NMOV * BB + 255) / 256, 256>>>(idx1, out, 2);

    k_D      <<<(NTRI * BB + 255) / 256, 256>>>(tri, 1);
    k_gemm   <<<(NMOV / 16) * KSPLIT, 128>>>(Vf);
    k_ssq    <<<(NMOV * BB + 255) / 256, 256>>>();
    k_update <<<(NMOV * BB + 255) / 256, 256>>>(idx1, out, 1);

    k_D      <<<(NTRI * BB + 255) / 256, 256>>>(tri, 0);
    k_gemm   <<<(NMOV / 16) * KSPLIT, 128>>>(Vf);
    k_ssq    <<<(NMOV * BB + 255) / 256, 256>>>();
    k_update <<<(NMOV * BB + 255) / 256, 256>>>(idx1, out, 0);
}